// round 3
// baseline (speedup 1.0000x reference)
#include <cuda_runtime.h>

#define BATCH  8
#define HWDIM  64
#define CCH    256
#define RED    64
#define EE     144     // K*K*G = 9*16
#define TILE_H 8
#define TILE_W 4
#define NPX    32      // pixels per CTA
#define NTHR   256

// SMEM layout (float offsets)
#define XH_STRIDE  260                   // 256 + 4 pad
#define HALO_W     6                     // TILE_W + 2
#define HALO_SP    60                    // 10 * 6
#define OFF_XH     0                     // 60 * 260 = 15600
#define OFF_WGT    15600                 // 32 * 144 = 4608
#define OFF_MID    20208                 // 32 * 68  = 2176
#define MID_STRIDE 68
#define SMEM_FLOATS 22384
#define SMEM_BYTES (SMEM_FLOATS * 4)     // 89536 B -> 2 CTAs/SM

__device__ float g_W2T[EE * RED];        // W2 transposed: [e][d]

__global__ void w2_transpose_kernel(const float* __restrict__ W2)
{
    int i = blockIdx.x * 256 + threadIdx.x;     // i = d*144 + e
    if (i < RED * EE) {
        int d = i / EE;
        int e = i - d * EE;
        g_W2T[e * RED + d] = W2[i];
    }
}

__global__ void __launch_bounds__(NTHR, 2)
invo_fused_kernel(const float* __restrict__ x,
                  const float* __restrict__ W1,
                  const float* __restrict__ b1,
                  const float* __restrict__ b2,
                  float* __restrict__ out)
{
    extern __shared__ float s[];
    const int t  = threadIdx.x;
    const int bb = blockIdx.z;
    const int h0 = blockIdx.y * TILE_H;
    const int w0 = blockIdx.x * TILE_W;

    // ---- Phase 0: load 10x6 halo tile of x (zero-padded) ----
    #pragma unroll
    for (int it = 0; it < 15; it++) {
        int i4 = t + it * NTHR;            // 0..3839 float4s
        int c4 = i4 & 63;                  // 64 float4 per spatial pos
        int sp = i4 >> 6;                  // 0..59
        int r  = sp / HALO_W;
        int cl = sp - r * HALO_W;
        int gh = h0 - 1 + r;
        int gw = w0 - 1 + cl;
        float4 v = make_float4(0.f, 0.f, 0.f, 0.f);
        if ((unsigned)gh < HWDIM && (unsigned)gw < HWDIM)
            v = *(const float4*)(x + ((size_t)((bb * HWDIM + gh) * HWDIM + gw) * CCH) + c4 * 4);
        *(float4*)(s + OFF_XH + sp * XH_STRIDE + c4 * 4) = v;
    }
    __syncthreads();

    const int tm = t >> 4;   // 0..15 : pixel pair index (2 px each)
    const int tn = t & 15;   // 0..15

    // ---- Stage 1: mid[32px][64] = x_tile @ W1 + b1  (W1 via L1/L2) ----
    {
        float acc[2][4];
        {
            float4 bv = __ldg((const float4*)(b1 + tn * 4));
            acc[0][0] = bv.x; acc[0][1] = bv.y; acc[0][2] = bv.z; acc[0][3] = bv.w;
            acc[1][0] = bv.x; acc[1][1] = bv.y; acc[1][2] = bv.z; acc[1][3] = bv.w;
        }
        int spb[2];
        #pragma unroll
        for (int i = 0; i < 2; i++) {
            int px  = tm * 2 + i;
            int row = px >> 2;             // tile row (4 px per row)
            int col = px & 3;
            spb[i] = OFF_XH + ((row + 1) * HALO_W + col + 1) * XH_STRIDE;
        }
        #pragma unroll 4
        for (int k = 0; k < CCH; k += 4) {
            float4 xa[2];
            xa[0] = *(const float4*)(s + spb[0] + k);
            xa[1] = *(const float4*)(s + spb[1] + k);
            #pragma unroll
            for (int kk = 0; kk < 4; kk++) {
                float4 wv = __ldg((const float4*)(W1 + (k + kk) * RED + tn * 4));
                #pragma unroll
                for (int i = 0; i < 2; i++) {
                    float xv = (kk == 0) ? xa[i].x : (kk == 1) ? xa[i].y : (kk == 2) ? xa[i].z : xa[i].w;
                    acc[i][0] += xv * wv.x;
                    acc[i][1] += xv * wv.y;
                    acc[i][2] += xv * wv.z;
                    acc[i][3] += xv * wv.w;
                }
            }
        }
        #pragma unroll
        for (int i = 0; i < 2; i++)
            *(float4*)(s + OFF_MID + (tm * 2 + i) * MID_STRIDE + tn * 4) =
                make_float4(acc[i][0], acc[i][1], acc[i][2], acc[i][3]);
    }
    __syncthreads();

    // ---- Stage 2: wgt[32px][144] = mid @ W2 + b2  (W2T via L1, float4 dots) ----
    {
        float acc[2][9];
        #pragma unroll
        for (int j = 0; j < 9; j++) {
            float bv = __ldg(b2 + tn * 9 + j);
            acc[0][j] = bv;
            acc[1][j] = bv;
        }
        #pragma unroll 4
        for (int d = 0; d < RED; d += 4) {
            float4 ma[2];
            ma[0] = *(const float4*)(s + OFF_MID + (tm * 2 + 0) * MID_STRIDE + d);
            ma[1] = *(const float4*)(s + OFF_MID + (tm * 2 + 1) * MID_STRIDE + d);
            #pragma unroll
            for (int j = 0; j < 9; j++) {
                float4 wv = __ldg((const float4*)(g_W2T + (tn * 9 + j) * RED + d));
                acc[0][j] += ma[0].x * wv.x + ma[0].y * wv.y + ma[0].z * wv.z + ma[0].w * wv.w;
                acc[1][j] += ma[1].x * wv.x + ma[1].y * wv.y + ma[1].z * wv.z + ma[1].w * wv.w;
            }
        }
        #pragma unroll
        for (int i = 0; i < 2; i++)
            #pragma unroll
            for (int j = 0; j < 9; j++)
                s[OFF_WGT + (tm * 2 + i) * EE + tn * 9 + j] = acc[i][j];
    }
    __syncthreads();

    // ---- Stage 3: involution (8 warps = 8 tile rows) ----
    // out[px, ch=g*16+gc] = sum_k wgt[px, g*9+k] * xpad[px + off(ko), ch_src]
    // with f = ch*9 + k, ko = f>>8 (spatial tap), ch_src = f&255.
    {
        const int warp = t >> 5;
        const int lane = t & 31;
        const int pr   = warp;                               // tile row 0..7
        const int wgt_row = OFF_WGT + pr * TILE_W * EE;
        const int xrow = OFF_XH + pr * HALO_W * XH_STRIDE;   // halo row pr == tap di=0
        const size_t outrow = (size_t)((bb * HWDIM + h0 + pr) * HWDIM + w0) * CCH;
        #pragma unroll
        for (int j = 0; j < 8; j++) {
            int ch  = lane + 32 * j;
            int g   = ch >> 4;
            int gc  = ch & 15;
            int f0  = g * EE + gc * 9;
            int ko0 = f0 >> 8;
            int cs0 = f0 & 255;
            int tc  = 256 - cs0;                 // #taps before crossing a 256 boundary
            int di0 = (ko0 * 86) >> 8;           // ko0 / 3
            int dj0 = ko0 - 3 * di0;
            int ko1 = ko0 + 1;
            int di1 = (ko1 * 86) >> 8;
            int dj1 = ko1 - 3 * di1;
            int off0 = (di0 * HALO_W + dj0) * XH_STRIDE + cs0;
            int off1 = (di1 * HALO_W + dj1) * XH_STRIDE;
            int wbase = wgt_row + g * 9;
            #pragma unroll
            for (int pc = 0; pc < TILE_W; pc++) {
                int bx = xrow + pc * XH_STRIDE;
                int A0 = bx + off0;              // addr = A0 + k          (k <  tc)
                int A1 = bx + off1 - tc;         // addr = A1 + k          (k >= tc)
                float acc = 0.f;
                #pragma unroll
                for (int k = 0; k < 9; k++) {
                    float wv = s[wbase + pc * EE + k];
                    int addr = (k < tc) ? (A0 + k) : (A1 + k);
                    acc += wv * s[addr];
                }
                out[outrow + pc * CCH + ch] = acc;
            }
        }
    }
}

extern "C" void kernel_launch(void* const* d_in, const int* in_sizes, int n_in,
                              void* d_out, int out_size)
{
    (void)in_sizes; (void)n_in; (void)out_size;
    const float* x  = (const float*)d_in[0];
    const float* W1 = (const float*)d_in[1];
    const float* b1 = (const float*)d_in[2];
    const float* W2 = (const float*)d_in[3];
    const float* b2 = (const float*)d_in[4];
    float* out = (float*)d_out;

    w2_transpose_kernel<<<(RED * EE + 255) / 256, 256>>>(W2);

    cudaFuncSetAttribute(invo_fused_kernel,
                         cudaFuncAttributeMaxDynamicSharedMemorySize, SMEM_BYTES);
    dim3 grid(HWDIM / TILE_W, HWDIM / TILE_H, BATCH);   // (16, 8, 8) = 1024 CTAs
    invo_fused_kernel<<<grid, NTHR, SMEM_BYTES>>>(x, W1, b1, b2, out);
}

// round 5
// speedup vs baseline: 3.1560x; 3.1560x over previous
#include <cuda_runtime.h>
#include <cstdint>

#define BATCH  8
#define HWDIM  64
#define CCH    256
#define RED    64
#define EE     144     // K*K*G = 9*16
#define NTHR   256

// ---- smem layout (float offsets) ----
#define XH_STRIDE  260
#define OFF_XH     0                    // 100*260 = 26000
#define OFF_W1     26000                // 256*68 = 17408 (overlaid by WGT after stage1)
#define W1_STRIDE  68
#define OFF_WGT    26000                // 64*145 = 9280
#define WGT_STRIDE 145
#define OFF_W2     43408                // 64*152 = 9728
#define W2_STRIDE  152
#define OFF_MID    53136                // 64*68 = 4352
#define MID_STRIDE 68
#define OFF_B1     57488                // 64
#define OFF_B2     57552                // 144
#define SMEM_FLOATS 57696
#define SMEM_BYTES (SMEM_FLOATS * 4)    // 230784 B <= 227KB limit, 1 CTA/SM

// m16n8k8 tf32 mma: D += A(16x8 row) * B(8x8 col)
__device__ __forceinline__ void mma_tf32(float d[4],
    uint32_t a0, uint32_t a1, uint32_t a2, uint32_t a3,
    uint32_t b0, uint32_t b1)
{
    asm volatile(
        "mma.sync.aligned.m16n8k8.row.col.f32.tf32.tf32.f32 "
        "{%0,%1,%2,%3}, {%4,%5,%6,%7}, {%8,%9}, {%0,%1,%2,%3};"
        : "+f"(d[0]), "+f"(d[1]), "+f"(d[2]), "+f"(d[3])
        : "r"(a0), "r"(a1), "r"(a2), "r"(a3), "r"(b0), "r"(b1));
}

// split v into tf32-truncated hi (matches HW truncation) + exact residual lo
__device__ __forceinline__ void tf32_split(float v, uint32_t& hi, uint32_t& lo)
{
    uint32_t h = __float_as_uint(v) & 0xFFFFE000u;
    hi = h;
    lo = __float_as_uint(v - __uint_as_float(h));
}

__global__ void __launch_bounds__(NTHR, 1)
invo_mma_kernel(const float* __restrict__ x,
                const float* __restrict__ W1,
                const float* __restrict__ b1,
                const float* __restrict__ W2,
                const float* __restrict__ b2,
                float* __restrict__ out)
{
    extern __shared__ float s[];
    const int t  = threadIdx.x;
    const int bb = blockIdx.z;
    const int h0 = blockIdx.y * 8;
    const int w0 = blockIdx.x * 8;

    // ---- Phase 0: halo 10x10x256 (zero-padded), W1, W2, biases ----
    #pragma unroll
    for (int it = 0; it < 25; it++) {
        int i4 = t + it * NTHR;            // 0..6399 float4s
        int c4 = i4 & 63;
        int sp = i4 >> 6;                  // 0..99
        int r  = sp / 10;
        int cl = sp - r * 10;
        int gh = h0 - 1 + r;
        int gw = w0 - 1 + cl;
        float4 v = make_float4(0.f, 0.f, 0.f, 0.f);
        if ((unsigned)gh < HWDIM && (unsigned)gw < HWDIM)
            v = *(const float4*)(x + ((size_t)((bb * HWDIM + gh) * HWDIM + gw) * CCH) + c4 * 4);
        *(float4*)(s + OFF_XH + sp * XH_STRIDE + c4 * 4) = v;
    }
    #pragma unroll
    for (int it = 0; it < 16; it++) {      // W1 [256 k][64 n] -> stride 68
        int i4 = t + it * NTHR;            // 0..4095
        int k  = i4 >> 4, n4 = i4 & 15;
        float4 v = *(const float4*)(W1 + i4 * 4);
        *(float4*)(s + OFF_W1 + k * W1_STRIDE + n4 * 4) = v;
    }
    #pragma unroll
    for (int it = 0; it < 9; it++) {       // W2 [64 d][144 e] -> stride 152
        int i4 = t + it * NTHR;            // 0..2303
        if (i4 < 2304) {
            int d = i4 / 36, e4 = i4 - d * 36;
            float4 v = *(const float4*)(W2 + i4 * 4);
            *(float4*)(s + OFF_W2 + d * W2_STRIDE + e4 * 4) = v;
        }
    }
    if (t < RED) s[OFF_B1 + t] = b1[t];
    if (t < EE)  s[OFF_B2 + t] = b2[t];
    __syncthreads();

    const int warp = t >> 5, lane = t & 31;
    const int gid = lane >> 2, t4 = lane & 3;

    // ---- Stage 1: mid[64px][64] = x @ W1 + b1   (3x tf32 mma) ----
    {
        const int m0 = (warp >> 1) * 16;           // mtile
        const int nb = (warp & 1) * 32;            // n half
        const int px0 = m0 + gid, px1 = px0 + 8;
        const int sp0 = OFF_XH + (((px0 >> 3) + 1) * 10 + (px0 & 7) + 1) * XH_STRIDE;
        const int sp1 = OFF_XH + (((px1 >> 3) + 1) * 10 + (px1 & 7) + 1) * XH_STRIDE;
        float D[4][4];
        #pragma unroll
        for (int nt = 0; nt < 4; nt++)
            #pragma unroll
            for (int i = 0; i < 4; i++) D[nt][i] = 0.f;

        #pragma unroll 4
        for (int k0 = 0; k0 < CCH; k0 += 8) {
            uint32_t ah[4], al[4];
            tf32_split(s[sp0 + k0 + t4],     ah[0], al[0]);
            tf32_split(s[sp1 + k0 + t4],     ah[1], al[1]);
            tf32_split(s[sp0 + k0 + t4 + 4], ah[2], al[2]);
            tf32_split(s[sp1 + k0 + t4 + 4], ah[3], al[3]);
            #pragma unroll
            for (int nt = 0; nt < 4; nt++) {
                int n = nb + nt * 8 + gid;
                uint32_t bh0, bl0, bh1, bl1;
                tf32_split(s[OFF_W1 + (k0 + t4) * W1_STRIDE + n],     bh0, bl0);
                tf32_split(s[OFF_W1 + (k0 + t4 + 4) * W1_STRIDE + n], bh1, bl1);
                mma_tf32(D[nt], al[0], al[1], al[2], al[3], bh0, bh1);
                mma_tf32(D[nt], ah[0], ah[1], ah[2], ah[3], bl0, bl1);
                mma_tf32(D[nt], ah[0], ah[1], ah[2], ah[3], bh0, bh1);
            }
        }
        #pragma unroll
        for (int nt = 0; nt < 4; nt++) {
            int n0 = nb + nt * 8 + 2 * t4;
            float bia0 = s[OFF_B1 + n0], bia1 = s[OFF_B1 + n0 + 1];
            *(float2*)(s + OFF_MID + (m0 + gid) * MID_STRIDE + n0) =
                make_float2(D[nt][0] + bia0, D[nt][1] + bia1);
            *(float2*)(s + OFF_MID + (m0 + gid + 8) * MID_STRIDE + n0) =
                make_float2(D[nt][2] + bia0, D[nt][3] + bia1);
        }
    }
    __syncthreads();

    // ---- Stage 2: wgt[64px][144] = mid @ W2 + b2  (3x tf32 mma; wgt over W1) ----
    {
        const int m0 = (warp >> 1) * 16;
        const int eb = (warp & 1) * 72;            // 9 ntiles of 8
        #pragma unroll
        for (int ch = 0; ch < 3; ch++) {           // ntile chunks of 3
            float D[3][4];
            #pragma unroll
            for (int j = 0; j < 3; j++)
                #pragma unroll
                for (int i = 0; i < 4; i++) D[j][i] = 0.f;

            #pragma unroll
            for (int k0 = 0; k0 < RED; k0 += 8) {
                uint32_t ah[4], al[4];
                tf32_split(s[OFF_MID + (m0 + gid)     * MID_STRIDE + k0 + t4],     ah[0], al[0]);
                tf32_split(s[OFF_MID + (m0 + gid + 8) * MID_STRIDE + k0 + t4],     ah[1], al[1]);
                tf32_split(s[OFF_MID + (m0 + gid)     * MID_STRIDE + k0 + t4 + 4], ah[2], al[2]);
                tf32_split(s[OFF_MID + (m0 + gid + 8) * MID_STRIDE + k0 + t4 + 4], ah[3], al[3]);
                #pragma unroll
                for (int j = 0; j < 3; j++) {
                    int e = eb + (ch * 3 + j) * 8 + gid;
                    uint32_t bh0, bl0, bh1, bl1;
                    tf32_split(s[OFF_W2 + (k0 + t4) * W2_STRIDE + e],     bh0, bl0);
                    tf32_split(s[OFF_W2 + (k0 + t4 + 4) * W2_STRIDE + e], bh1, bl1);
                    mma_tf32(D[j], al[0], al[1], al[2], al[3], bh0, bh1);
                    mma_tf32(D[j], ah[0], ah[1], ah[2], ah[3], bl0, bl1);
                    mma_tf32(D[j], ah[0], ah[1], ah[2], ah[3], bh0, bh1);
                }
            }
            #pragma unroll
            for (int j = 0; j < 3; j++) {
                int e0 = eb + (ch * 3 + j) * 8 + 2 * t4;
                float bb0 = s[OFF_B2 + e0], bb1 = s[OFF_B2 + e0 + 1];
                s[OFF_WGT + (m0 + gid)     * WGT_STRIDE + e0]     = D[j][0] + bb0;
                s[OFF_WGT + (m0 + gid)     * WGT_STRIDE + e0 + 1] = D[j][1] + bb1;
                s[OFF_WGT + (m0 + gid + 8) * WGT_STRIDE + e0]     = D[j][2] + bb0;
                s[OFF_WGT + (m0 + gid + 8) * WGT_STRIDE + e0 + 1] = D[j][3] + bb1;
            }
        }
    }
    __syncthreads();

    // ---- Stage 3: involution, float4 halo reads, direct STG ----
    // ch = g*16 + gc; f = g*144 + gc*9 + k; ko = f>>8 (tap), ch_src = f&255.
    // Per (g): f4-index F = g*36 + idx (idx 0..35); crosses one 64-f4 boundary.
    {
        const int half = warp & 1, gset = warp >> 1;
        const int pr = half * 4 + (lane >> 3), pc = lane & 7;
        const int wbase = OFF_WGT + (pr * 8 + pc) * WGT_STRIDE;
        const int xb = OFF_XH + (pr * 10 + pc) * XH_STRIDE;   // tap (di=0,dj=0)
        float* op = out + ((size_t)((bb * HWDIM + h0 + pr) * HWDIM + (w0 + pc))) * CCH;
        #pragma unroll
        for (int gi = 0; gi < 4; gi++) {
            int g = gset * 4 + gi;
            float wv[9];
            #pragma unroll
            for (int k = 0; k < 9; k++) wv[k] = s[wbase + g * 9 + k];
            int F0g = g * 36;
            int ko0 = F0g >> 6;
            int cs0 = F0g & 63;
            int tc  = 64 - cs0;                    // idx count before boundary
            int di0 = (ko0 * 11) >> 5, dj0 = ko0 - 3 * di0;
            int ko1 = ko0 + 1;
            int di1 = (ko1 * 11) >> 5, dj1 = ko1 - 3 * di1;
            int A0 = xb + (di0 * 10 + dj0) * XH_STRIDE + cs0 * 4;   // + idx*4
            int A1 = xb + (di1 * 10 + dj1) * XH_STRIDE - tc * 4;    // + idx*4 (idx>=tc)
            #pragma unroll
            for (int c = 0; c < 4; c++) {
                float acc[4] = {0.f, 0.f, 0.f, 0.f};
                #pragma unroll
                for (int j = 0; j < 9; j++) {
                    const int idx = c * 9 + j;
                    int addr = ((idx < tc) ? A0 : A1) + idx * 4;
                    const float4 xv = *(const float4*)(s + addr);
                    const int fl = idx * 4;        // float index within group's 144
                    acc[(fl + 0) / 9 - c * 4] += wv[(fl + 0) % 9] * xv.x;
                    acc[(fl + 1) / 9 - c * 4] += wv[(fl + 1) % 9] * xv.y;
                    acc[(fl + 2) / 9 - c * 4] += wv[(fl + 2) % 9] * xv.z;
                    acc[(fl + 3) / 9 - c * 4] += wv[(fl + 3) % 9] * xv.w;
                }
                *(float4*)(op + g * 16 + c * 4) =
                    make_float4(acc[0], acc[1], acc[2], acc[3]);
            }
        }
    }
}

extern "C" void kernel_launch(void* const* d_in, const int* in_sizes, int n_in,
                              void* d_out, int out_size)
{
    (void)in_sizes; (void)n_in; (void)out_size;
    const float* x  = (const float*)d_in[0];
    const float* W1 = (const float*)d_in[1];
    const float* b1 = (const float*)d_in[2];
    const float* W2 = (const float*)d_in[3];
    const float* b2 = (const float*)d_in[4];
    float* out = (float*)d_out;

    cudaFuncSetAttribute(invo_mma_kernel,
                         cudaFuncAttributeMaxDynamicSharedMemorySize, SMEM_BYTES);
    dim3 grid(HWDIM / 8, HWDIM / 8, BATCH);   // (8, 8, 8) = 512 CTAs
    invo_mma_kernel<<<grid, NTHR, SMEM_BYTES>>>(x, W1, b1, W2, b2, out);
}